// round 1
// baseline (speedup 1.0000x reference)
#include <cuda_runtime.h>
#include <cstdint>

// ---------------- problem constants ----------------
#define B_   8
#define S_   4096
#define D_   2048
#define M_   (B_*S_)        // 32768 tokens
#define E1_  (3*D_)         // 6144
#define HALFPAIRS 512       // roped pairs: rot_dim = D/2 = 1024 -> 512 pairs
#define NCHUNK 32           // sequence chunks per batch for reduction
#define CHUNKS_S (S_/NCHUNK) // 128

// ---------------- scratch (device globals; no runtime alloc) ----------------
__device__ float g_Q [67108864];   // [M, D] fp32
__device__ float g_K [67108864];
__device__ float g_V [67108864];
__device__ float g_Yb[67108864];
__device__ float g_Apart[(size_t)B_ * NCHUNK * D_];  // per-chunk partials
__device__ float g_A[B_ * D_];

// -log2(10000)/512
#define NEG_L2T_OVER_512 (-0.025952563241307517)

// ---------------- PTX helpers ----------------
__device__ __forceinline__ void cp_async16(void* sdst, const void* gsrc) {
    unsigned saddr = (unsigned)__cvta_generic_to_shared(sdst);
    asm volatile("cp.async.cg.shared.global [%0], [%1], 16;" :: "r"(saddr), "l"(gsrc));
}
#define CP_COMMIT() asm volatile("cp.async.commit_group;")
#define CP_WAIT1()  asm volatile("cp.async.wait_group 1;")

__device__ __forceinline__ unsigned f2tf32(float x) {
    unsigned r;
    asm volatile("cvt.rna.tf32.f32 %0, %1;" : "=r"(r) : "f"(x));
    return r;
}

__device__ __forceinline__ void mma_tf32(float c[4], const unsigned a[4],
                                         unsigned b0, unsigned b1) {
    asm volatile(
        "mma.sync.aligned.m16n8k8.row.col.f32.tf32.tf32.f32 "
        "{%0,%1,%2,%3},{%4,%5,%6,%7},{%8,%9},{%0,%1,%2,%3};"
        : "+f"(c[0]), "+f"(c[1]), "+f"(c[2]), "+f"(c[3])
        : "r"(a[0]), "r"(a[1]), "r"(a[2]), "r"(a[3]), "r"(b0), "r"(b1));
}

// ---------------- TF32 GEMM: C[M,N] = A[M,K] * B[N,K]^T (+ epilogue) --------
// MODE 0: A = X (param), outputs routed to g_Q / g_K / g_V by column section,
//         bias = b_in.
// MODE 1: A = g_Yb, out = d_out, epilogue adds b_out + X residual.
#define BM 128
#define BN 128
#define BK 16
#define LDSR 20                 // BK + 4 pad floats (keeps 16B align, kills conflicts)
#define KT (D_/BK)              // 128 k-iterations

template <int MODE>
__global__ __launch_bounds__(256, 2)
void gemm_tf32(const float* __restrict__ Aparam,
               const float* __restrict__ Bg,
               const float* __restrict__ bias,
               const float* __restrict__ Xres,
               float* __restrict__ outParam)
{
    __shared__ float As[2][BM * LDSR];
    __shared__ float Bs[2][BN * LDSR];

    const float* __restrict__ Ag = (MODE == 0) ? Aparam : g_Yb;

    const int tid  = threadIdx.x;
    const int lane = tid & 31;
    const int warp = tid >> 5;
    const int wm   = (warp >> 1) * 32;   // warp M offset within tile (4 warps in M)
    const int wn   = (warp & 1) * 64;    // warp N offset within tile (2 warps in N)
    const int gID  = lane >> 2;          // 0..7
    const int tig  = lane & 3;           // 0..3

    const int blockN = blockIdx.x * BN;
    const int blockM = blockIdx.y * BM;

    // Global->shared staging: each thread moves 2x16B for A and 2x16B for B.
    const int ldRow = tid >> 2;          // 0..63
    const int ldCol = (tid & 3) * 4;     // float offset (16B chunks)

    float c[2][8][4];
    #pragma unroll
    for (int i = 0; i < 2; i++)
        #pragma unroll
        for (int j = 0; j < 8; j++)
            #pragma unroll
            for (int k = 0; k < 4; k++) c[i][j][k] = 0.f;

    // prologue: load tile 0 into buffer 0
    {
        const int k0 = 0;
        #pragma unroll
        for (int i = 0; i < 2; i++) {
            const int row = ldRow + i * 64;
            cp_async16(&As[0][row * LDSR + ldCol],
                       Ag + (size_t)(blockM + row) * D_ + k0 + ldCol);
            cp_async16(&Bs[0][row * LDSR + ldCol],
                       Bg + (size_t)(blockN + row) * D_ + k0 + ldCol);
        }
    }
    CP_COMMIT();

    int buf = 0;
    for (int kt = 0; kt < KT; ++kt) {
        if (kt + 1 < KT) {
            const int k0 = (kt + 1) * BK;
            const int nb = buf ^ 1;
            #pragma unroll
            for (int i = 0; i < 2; i++) {
                const int row = ldRow + i * 64;
                cp_async16(&As[nb][row * LDSR + ldCol],
                           Ag + (size_t)(blockM + row) * D_ + k0 + ldCol);
                cp_async16(&Bs[nb][row * LDSR + ldCol],
                           Bg + (size_t)(blockN + row) * D_ + k0 + ldCol);
            }
        }
        CP_COMMIT();          // committed even when empty -> uniform wait semantics
        CP_WAIT1();           // tile kt guaranteed resident
        __syncthreads();

        #pragma unroll
        for (int ks = 0; ks < 2; ++ks) {
            const int kk = ks * 8;
            unsigned a[2][4];
            #pragma unroll
            for (int mi = 0; mi < 2; ++mi) {
                const float* ap = &As[buf][(wm + mi * 16 + gID) * LDSR + kk + tig];
                a[mi][0] = f2tf32(ap[0]);
                a[mi][1] = f2tf32(ap[8 * LDSR]);
                a[mi][2] = f2tf32(ap[4]);
                a[mi][3] = f2tf32(ap[8 * LDSR + 4]);
            }
            #pragma unroll
            for (int ni = 0; ni < 8; ++ni) {
                const float* bp = &Bs[buf][(wn + ni * 8 + gID) * LDSR + kk + tig];
                const unsigned b0 = f2tf32(bp[0]);
                const unsigned b1 = f2tf32(bp[4]);
                mma_tf32(c[0][ni], a[0], b0, b1);
                mma_tf32(c[1][ni], a[1], b0, b1);
            }
        }
        __syncthreads();
        buf ^= 1;
    }

    // ---------------- epilogue ----------------
    float* __restrict__ dst;
    int colBase;
    if (MODE == 0) {
        const int sect = blockN >> 11;          // 0:Q 1:K 2:V (BN divides 2048)
        dst = (sect == 0) ? g_Q : ((sect == 1) ? g_K : g_V);
        colBase = blockN & (D_ - 1);
    } else {
        dst = outParam;
        colBase = blockN;
    }

    #pragma unroll
    for (int mi = 0; mi < 2; ++mi) {
        const int rA = blockM + wm + mi * 16 + gID;
        const int rB = rA + 8;
        #pragma unroll
        for (int ni = 0; ni < 8; ++ni) {
            const int e  = blockN + wn + ni * 8 + tig * 2;   // global bias col
            const int el = colBase + wn + ni * 8 + tig * 2;  // col in dst
            const float bv0 = __ldg(&bias[e]);
            const float bv1 = __ldg(&bias[e + 1]);
            float2 v0 = make_float2(c[mi][ni][0] + bv0, c[mi][ni][1] + bv1);
            float2 v1 = make_float2(c[mi][ni][2] + bv0, c[mi][ni][3] + bv1);
            if (MODE == 1) {
                const float2 x0 = *(const float2*)(Xres + (size_t)rA * D_ + el);
                const float2 x1 = *(const float2*)(Xres + (size_t)rB * D_ + el);
                v0.x += x0.x; v0.y += x0.y;
                v1.x += x1.x; v1.y += x1.y;
            }
            *(float2*)(dst + (size_t)rA * D_ + el) = v0;
            *(float2*)(dst + (size_t)rB * D_ + el) = v1;
        }
    }
}

// -------- reduction stage 1: per (batch, chunk) partial of fm(rope(K)) * V ---
__global__ __launch_bounds__(256)
void reduce_A_kernel()
{
    const int b     = blockIdx.x >> 5;
    const int chunk = blockIdx.x & 31;
    const int tid   = threadIdx.x;
    __shared__ float red[8];

    float acc[8];
    #pragma unroll
    for (int j = 0; j < 8; j++) acc[j] = 0.f;

    // pairs handled by this thread: p = tid + 256*j ; roped iff p < 512 (j<2)
    float invf[2];
    #pragma unroll
    for (int j = 0; j < 2; j++) {
        const int p = tid + 256 * j;
        invf[j] = exp2f((float)p * (float)NEG_L2T_OVER_512);
    }

    const int s0 = chunk * CHUNKS_S;
    for (int s = s0; s < s0 + CHUNKS_S; ++s) {
        const size_t rowoff = ((size_t)b * S_ + s) * D_;
        float kr[8];
        float sq = 0.f;
        #pragma unroll
        for (int j = 0; j < 4; ++j) {
            const int p = tid + 256 * j;
            const float2 kv = *(const float2*)(g_K + rowoff + 2 * p);
            float x0 = kv.x, x1 = kv.y;
            if (j < 2) {   // roped region (p < 512 guaranteed: tid<256)
                float sn, cs;
                sincosf((float)s * invf[j], &sn, &cs);
                const float r0 = x0 * cs - x1 * sn;
                const float r1 = x1 * cs + x0 * sn;
                x0 = r0; x1 = r1;
            }
            kr[2 * j] = x0; kr[2 * j + 1] = x1;
            sq = fmaf(x0, x0, fmaf(x1, x1, sq));
        }
        // block-wide norm reduction
        #pragma unroll
        for (int o = 16; o; o >>= 1) sq += __shfl_xor_sync(0xffffffffu, sq, o);
        if ((tid & 31) == 0) red[tid >> 5] = sq;
        __syncthreads();
        const float tot = red[0] + red[1] + red[2] + red[3]
                        + red[4] + red[5] + red[6] + red[7];
        __syncthreads();
        const float inv_n = 1.f / fmaxf(sqrtf(tot), 1e-12f);

        #pragma unroll
        for (int j = 0; j < 4; ++j) {
            const int p = tid + 256 * j;
            const float2 vv = *(const float2*)(g_V + rowoff + 2 * p);
            acc[2 * j]     = fmaf(kr[2 * j]     * inv_n, vv.x, acc[2 * j]);
            acc[2 * j + 1] = fmaf(kr[2 * j + 1] * inv_n, vv.y, acc[2 * j + 1]);
        }
    }
    // deterministic: write partials, no atomics
    float* dstp = g_Apart + ((size_t)b * NCHUNK + chunk) * D_;
    #pragma unroll
    for (int j = 0; j < 4; ++j) {
        const int p = tid + 256 * j;
        *(float2*)(dstp + 2 * p) = make_float2(acc[2 * j], acc[2 * j + 1]);
    }
}

// -------- reduction stage 2: fixed-order finalize ----------------------------
__global__ void finalize_A_kernel()
{
    const int i = blockIdx.x * 256 + threadIdx.x;   // i < B_*D_ = 16384
    const int b = i >> 11;
    const int d = i & (D_ - 1);
    float s = 0.f;
    #pragma unroll
    for (int c = 0; c < NCHUNK; ++c)
        s += g_Apart[((size_t)b * NCHUNK + c) * D_ + d];
    g_A[i] = s;
}

// -------- Yb = A (broadcast over s) * rope(Q) --------------------------------
__global__ __launch_bounds__(256)
void yb_kernel()
{
    const int m = blockIdx.x;          // token index
    const int b = m >> 12;             // /4096
    const int s = m & (S_ - 1);
    const int tid = threadIdx.x;
    const size_t rowoff = (size_t)m * D_;
    const float* Arow = g_A + b * D_;

    #pragma unroll
    for (int j = 0; j < 4; ++j) {
        const int p = tid + 256 * j;
        const float2 q = *(const float2*)(g_Q + rowoff + 2 * p);
        float x0 = q.x, x1 = q.y;
        if (j < 2) {
            const float invf = exp2f((float)p * (float)NEG_L2T_OVER_512);
            float sn, cs;
            sincosf((float)s * invf, &sn, &cs);
            const float r0 = x0 * cs - x1 * sn;
            const float r1 = x1 * cs + x0 * sn;
            x0 = r0; x1 = r1;
        }
        const float2 a = *(const float2*)(Arow + 2 * p);
        *(float2*)(g_Yb + rowoff + 2 * p) = make_float2(a.x * x0, a.y * x1);
    }
}

// ---------------- launch ------------------------------------------------------
extern "C" void kernel_launch(void* const* d_in, const int* in_sizes, int n_in,
                              void* d_out, int out_size)
{
    const float* X     = (const float*)d_in[0];   // [8,4096,2048]
    const float* W_in  = (const float*)d_in[1];   // [6144,2048]
    const float* b_in  = (const float*)d_in[2];   // [6144]
    const float* W_out = (const float*)d_in[3];   // [2048,2048]
    const float* b_out = (const float*)d_in[4];   // [2048]
    float* out = (float*)d_out;

    // 1) QKV = X @ W_in^T + b_in  ->  g_Q, g_K, g_V
    gemm_tf32<0><<<dim3(E1_ / BN, M_ / BM), 256>>>(X, W_in, b_in, nullptr, nullptr);

    // 2) A = sum_s fm(rope(K)) * V   (two-stage, deterministic)
    reduce_A_kernel<<<B_ * NCHUNK, 256>>>();
    finalize_A_kernel<<<(B_ * D_) / 256, 256>>>();

    // 3) Yb = A ⊙ rope(Q)
    yb_kernel<<<M_, 256>>>();

    // 4) out = Yb @ W_out^T + b_out + X
    gemm_tf32<1><<<dim3(D_ / BN, M_ / BM), 256>>>(nullptr, W_out, b_out, X, out);

    (void)in_sizes; (void)n_in; (void)out_size;
}